// round 16
// baseline (speedup 1.0000x reference)
#include <cuda_runtime.h>
#include <cstdint>

// Problem constants
#define BB 32
#define NN 4096
#define EE 64
#define CC 256
#define TM 128           // x rows per block tile
#define TPB 256
#define SXS 72           // X smem row stride (floats): 72 % 32 == 8 -> LDS.64 conflict-free
#define EPS 1e-6f
#define LN2F 0.6931471805599453f

typedef unsigned long long ull;

__device__ float  g_inv_msum[BB];
__device__ float  g_c2[CC];                // ||c||^2
__device__ float  g_sc[CC];                // 2/(1-||c||^2)
__device__ float4 g_cpack4[8 * 16 * 32];   // B frags paired: [kt][ng2][lane] ->
                                           // {B(k,na), B(k+4,na), B(k,nb), B(k+4,nb)}, nb=na+8

#define SQRT_APPROX(out, in) \
    asm("sqrt.approx.f32 %0, %1;" : "=f"(out) : "f"(in))
#define LG2_APPROX(out, in) \
    asm("lg2.approx.f32 %0, %1;" : "=f"(out) : "f"(in))

// ---- packed f32x2 helpers (baseline sm_100-family PTX; works on sm_103) ----
__device__ __forceinline__ ull pk2(float lo, float hi) {
    ull r; asm("mov.b64 %0, {%1, %2};" : "=l"(r) : "f"(lo), "f"(hi)); return r;
}
__device__ __forceinline__ void upk2(ull v, float& lo, float& hi) {
    asm("mov.b64 {%0, %1}, %2;" : "=f"(lo), "=f"(hi) : "l"(v));
}
__device__ __forceinline__ ull add2(ull a, ull b) {
    ull r; asm("add.rn.f32x2 %0, %1, %2;" : "=l"(r) : "l"(a), "l"(b)); return r;
}
__device__ __forceinline__ ull mul2(ull a, ull b) {
    ull r; asm("mul.rn.f32x2 %0, %1, %2;" : "=l"(r) : "l"(a), "l"(b)); return r;
}
__device__ __forceinline__ ull fma2(ull a, ull b, ull c) {
    ull r; asm("fma.rn.f32x2 %0, %1, %2, %3;" : "=l"(r) : "l"(a), "l"(b), "l"(c)); return r;
}

// tf32 HMMA m16n8k8 (baseline PTX, works on plain sm_103 target)
__device__ __forceinline__ void mma_tf32(float* d, const uint32_t* a, const uint32_t* b) {
    asm volatile(
        "mma.sync.aligned.m16n8k8.row.col.f32.tf32.tf32.f32 "
        "{%0,%1,%2,%3}, {%4,%5,%6,%7}, {%8,%9}, {%0,%1,%2,%3};"
        : "+f"(d[0]), "+f"(d[1]), "+f"(d[2]), "+f"(d[3])
        : "r"(a[0]), "r"(a[1]), "r"(a[2]), "r"(a[3]), "r"(b[0]), "r"(b[1]));
}

// packed acosh epilogue: 2 columns at once.
// dot2={dot_c0,dot_c1}; x2b/ivb/lmb = broadcast row params; c2p/scp = col pairs.
__device__ __forceinline__ ull xform2(ull dot2, ull x2b, ull ivb, ull lmb,
                                      ull c2p, ull scp) {
    const ull neg2 = pk2(-2.0f, -2.0f);
    const ull one2 = pk2(1.0f, 1.0f);
    ull base = add2(x2b, c2p);              // x2 + c2
    ull sq = fma2(neg2, dot2, base);        // x2 + c2 - 2 dot (may be <0: clamped below)
    ull t = mul2(sq, mul2(ivb, scp));
    float t0, t1; upk2(t, t0, t1);
    t0 = fmaxf(t0, EPS); t1 = fmaxf(t1, EPS);
    ull t2 = pk2(t0, t1);
    ull si = fma2(t2, t2, add2(t2, t2));    // t^2 + 2t
    float u0, u1; upk2(si, u0, u1);
    float s0, s1; SQRT_APPROX(s0, u0); SQRT_APPROX(s1, u1);
    ull arg = add2(add2(one2, t2), pk2(s0, s1));
    float a0, a1; upk2(arg, a0, a1);
    float l0, l1; LG2_APPROX(l0, a0); LG2_APPROX(l1, a1);
    return mul2(pk2(l0, l1), lmb);          // lg2(arg) * mask*ln2
}

// ---------------------------------------------------------------------------
// Prep: 1/sum(mask) per batch, zero graph_dist; cpack4 spread over all blocks,
// centroid params on block 0.
// ---------------------------------------------------------------------------
__global__ void prep_kernel(const float* __restrict__ mask,
                            const float* __restrict__ cent,
                            float* __restrict__ gd) {
    int b = blockIdx.x;
    int tid = threadIdx.x;

    float local = 0.f;
    const float4* m4 = reinterpret_cast<const float4*>(mask + (size_t)b * NN);
    for (int i = tid; i < NN / 4; i += TPB) {
        float4 v = m4[i];
        local += (v.x + v.y) + (v.z + v.w);
    }
#pragma unroll
    for (int s = 16; s > 0; s >>= 1)
        local += __shfl_xor_sync(0xffffffffu, local, s);
    __shared__ float wsum[8];
    if ((tid & 31) == 0) wsum[tid >> 5] = local;
    __syncthreads();
    if (tid == 0) {
        float t = 0.f;
#pragma unroll
        for (int w = 0; w < 8; w++) t += wsum[w];
        g_inv_msum[b] = 1.0f / t;
    }
    gd[b * CC + tid] = 0.0f;

    // B-fragment packing: 4096 float4 entries, 128 per block
    if (tid < 128) {
        int e = b * 128 + tid;
        int lane = e & 31;
        int ng2 = (e >> 5) & 15;
        int kt = e >> 9;
        int na = ng2 * 16 + (lane >> 2);
        int nb = na + 8;
        int k = kt * 8 + (lane & 3);
        g_cpack4[e] = make_float4(cent[na * EE + k], cent[na * EE + k + 4],
                                  cent[nb * EE + k], cent[nb * EE + k + 4]);
    }

    if (b == 0) {   // centroid params (split arrays for packed LDS.64 pairs)
        const float4* cr = reinterpret_cast<const float4*>(cent + (size_t)tid * EE);
        float c2 = 0.f;
#pragma unroll
        for (int i = 0; i < 16; i++) {
            float4 v = cr[i];
            c2 = fmaf(v.x, v.x, c2); c2 = fmaf(v.y, v.y, c2);
            c2 = fmaf(v.z, v.z, c2); c2 = fmaf(v.w, v.w, c2);
        }
        g_c2[tid] = c2;
        g_sc[tid] = __fdividef(2.0f, 1.0f - c2);
    }
}

// ---------------------------------------------------------------------------
// Main: tf32 mma.sync GEMM (X[128,64] @ C[256,64]^T) + packed acosh epilogue.
// X smem layout: per row, each kt-group of 8 cols stored as pairs (k, k+4):
//   pos(kt*8 + u) = kt*8 + 2*(u&3) + (u>>2)   -> A fragments load as LDS.64.
// grid = (NN/TM, BB), 256 threads (8 warps: mw=wid%4 rows, nw=wid/4 col half)
// ---------------------------------------------------------------------------
__global__ void __launch_bounds__(TPB, 2)
centroid_dist_kernel(const float* __restrict__ x,
                     const float* __restrict__ mask,
                     float* __restrict__ gd,
                     float* __restrict__ dist) {
    __shared__ float  sx[TM * SXS];            // X tile, permuted pairs, stride 72
    __shared__ float4 srp[TM];                 // {x2, 1/(1-x2), mask*ln2, -}
    __shared__ __align__(16) float sc2[CC];    // c2 (packed-pair loads)
    __shared__ __align__(16) float ssc[CC];    // 2/(1-c2)

    const int tid = threadIdx.x;
    const int wid = tid >> 5;
    const int lane = tid & 31;
    const int b = blockIdx.y;
    const int n0 = blockIdx.x * TM;

    // ---- load X tile into permuted smem ----
    {
        const float4* gx = reinterpret_cast<const float4*>(
            x + ((size_t)b * NN + n0) * EE);
#pragma unroll
        for (int i = 0; i < (TM * 16) / TPB; i++) {   // 8
            int idx = tid + TPB * i;
            int r = idx >> 4, c4 = idx & 15;
            int kt = c4 >> 1, odd = c4 & 1;
            float4 v = gx[idx];
            float* d = sx + r * SXS + kt * 8 + odd;
            d[0] = v.x; d[2] = v.y; d[4] = v.z; d[6] = v.w;
        }
    }
    // ---- centroid params ----
    sc2[tid] = g_c2[tid];
    ssc[tid] = g_sc[tid];

    // ---- row params: two threads per row (gmem read, overlaps STS) ----
    {
        int r = tid >> 1;
        const float4* row4 = reinterpret_cast<const float4*>(
            x + ((size_t)b * NN + n0 + r) * EE) + (tid & 1) * 8;
        float s = 0.f;
#pragma unroll
        for (int k = 0; k < 8; k++) {
            float4 v = row4[k];
            s = fmaf(v.x, v.x, s); s = fmaf(v.y, v.y, s);
            s = fmaf(v.z, v.z, s); s = fmaf(v.w, v.w, s);
        }
        s += __shfl_xor_sync(0xffffffffu, s, 1);
        if (!(tid & 1))
            srp[r] = make_float4(s, __fdividef(1.0f, 1.0f - s),
                                 mask[(size_t)b * NN + n0 + r] * LN2F, 0.f);
    }
    __syncthreads();

    const int mw = wid & 3;          // row group (32 rows)
    const int nw = wid >> 2;         // col half (128 cols)
    const int rq = lane >> 2;        // lane/4
    const int rbase = mw * 32 + rq;

    // packed broadcast row params: idx 0=mt0 rowA, 1=mt0 rowB, 2=mt1 rowA, 3=mt1 rowB
    ull x2p[4], ivp[4], lmp[4];
    {
        const int roff[4] = {0, 8, 16, 24};
#pragma unroll
        for (int i = 0; i < 4; i++) {
            float4 rp = srp[rbase + roff[i]];
            x2p[i] = pk2(rp.x, rp.x);
            ivp[i] = pk2(rp.y, rp.y);
            lmp[i] = pk2(rp.z, rp.z);
        }
    }
    const float inv_m = g_inv_msum[b];

    const float* ap = sx + rbase * SXS + 2 * (lane & 3);

#pragma unroll 1
    for (int p = 0; p < 2; p++) {
        const int colbase = nw * 128 + p * 64;
        const int ng2_0 = colbase >> 4;       // 16-col group index

        float acc[2][8][4];
#pragma unroll
        for (int mt = 0; mt < 2; mt++)
#pragma unroll
            for (int nt = 0; nt < 8; nt++)
#pragma unroll
                for (int j = 0; j < 4; j++) acc[mt][nt][j] = 0.f;

#pragma unroll
        for (int kt = 0; kt < 8; kt++) {
            uint32_t a[2][4];
#pragma unroll
            for (int mt = 0; mt < 2; mt++) {
                const float* q = ap + mt * (16 * SXS) + kt * 8;
                float2 lo = *reinterpret_cast<const float2*>(q);            // {a0,a2}
                float2 hi = *reinterpret_cast<const float2*>(q + 8 * SXS);  // {a1,a3}
                a[mt][0] = __float_as_uint(lo.x);
                a[mt][2] = __float_as_uint(lo.y);
                a[mt][1] = __float_as_uint(hi.x);
                a[mt][3] = __float_as_uint(hi.y);
            }
            uint32_t bf[8][2];
            const float4* bp = g_cpack4 + ((size_t)(kt * 16 + ng2_0) * 32 + lane);
#pragma unroll
            for (int n2 = 0; n2 < 4; n2++) {   // 4 x LDG.128 -> 8 fragments
                float4 v = __ldg(&bp[n2 * 32]);
                bf[2 * n2][0] = __float_as_uint(v.x);
                bf[2 * n2][1] = __float_as_uint(v.y);
                bf[2 * n2 + 1][0] = __float_as_uint(v.z);
                bf[2 * n2 + 1][1] = __float_as_uint(v.w);
            }
#pragma unroll
            for (int mt = 0; mt < 2; mt++)
#pragma unroll
                for (int nt = 0; nt < 8; nt++)
                    mma_tf32(acc[mt][nt], a[mt], bf[nt]);
        }

        // ---- packed epilogue ----
        float* drow0 = dist + ((size_t)b * NN + n0 + mw * 32 + rq) * CC;
#pragma unroll
        for (int nt = 0; nt < 8; nt++) {
            const int c0 = colbase + nt * 8 + 2 * (lane & 3);   // even -> 8B aligned
            const ull c2p = *reinterpret_cast<const ull*>(&sc2[c0]);
            const ull scp = *reinterpret_cast<const ull*>(&ssc[c0]);
            ull csp = 0ULL;   // packed {cs_c0, cs_c1}
#pragma unroll
            for (int mt = 0; mt < 2; mt++) {
                const int ri = mt * 2;
                ull dA = xform2(pk2(acc[mt][nt][0], acc[mt][nt][1]),
                                x2p[ri], ivp[ri], lmp[ri], c2p, scp);
                ull dB = xform2(pk2(acc[mt][nt][2], acc[mt][nt][3]),
                                x2p[ri + 1], ivp[ri + 1], lmp[ri + 1], c2p, scp);

                float* r0p = drow0 + (size_t)(mt * 16) * CC + c0;
                *reinterpret_cast<ull*>(r0p) = dA;                      // STG.64
                *reinterpret_cast<ull*>(r0p + (size_t)8 * CC) = dB;     // STG.64
                csp = add2(csp, add2(dA, dB));
            }
            float cs0, cs1; upk2(csp, cs0, cs1);
            cs0 += __shfl_xor_sync(0xffffffffu, cs0, 4);
            cs0 += __shfl_xor_sync(0xffffffffu, cs0, 8);
            cs0 += __shfl_xor_sync(0xffffffffu, cs0, 16);
            cs1 += __shfl_xor_sync(0xffffffffu, cs1, 4);
            cs1 += __shfl_xor_sync(0xffffffffu, cs1, 8);
            cs1 += __shfl_xor_sync(0xffffffffu, cs1, 16);
            if (lane < 4) {
                atomicAdd(&gd[b * CC + c0], cs0 * inv_m);
                atomicAdd(&gd[b * CC + c0 + 1], cs1 * inv_m);
            }
        }
    }
}

// ---------------------------------------------------------------------------
extern "C" void kernel_launch(void* const* d_in, const int* in_sizes, int n_in,
                              void* d_out, int out_size) {
    const float* x = (const float*)d_in[0];      // node_repr (B,N,E)
    const float* mask = (const float*)d_in[1];   // mask (B,N,1)
    const float* cent = (const float*)d_in[2];   // centroid (C,E)

    float* out = (float*)d_out;
    float* gd = out;                 // graph_dist (B,C)
    float* dist = out + BB * CC;     // dist (B,N,C)

    prep_kernel<<<BB, TPB>>>(mask, cent, gd);
    dim3 grid(NN / TM, BB);
    centroid_dist_kernel<<<grid, TPB>>>(x, mask, gd, dist);
}